// round 3
// baseline (speedup 1.0000x reference)
#include <cuda_runtime.h>
#include <math_constants.h>

// Problem constants (fixed by setup_inputs)
#define S_LEN 2048
#define BATCH 4
#define HEADS 8
#define BH    (BATCH*HEADS)        // 32
#define HD    64
#define BM    64
#define BN    64
#define NQT   (S_LEN/BM)           // 32
#define NKT   (S_LEN/BN)           // 32
#define NTHREADS 128

#define KSTRIDE 65                 // padded stride for K / P tiles in smem
#define SMEM_FLOATS (BM*HD + BN*KSTRIDE + BN*HD)   // Q + K(=P alias) + V
#define SMEM_BYTES  (SMEM_FLOATS * 4)              // 49408

// ---------------- device scratch (no allocations allowed) ----------------
__device__ unsigned int  g_mask[S_LEN][S_LEN/32];   // 512 KB museformer bitmask
__device__ unsigned int  g_occ[NQT];                // per-q-tile k-tile occupancy bitmap
__device__ float         g_vmean[BH][HD];           // fallback: mean of V over S
__device__ unsigned char g_pad[BATCH*S_LEN];        // canonical uint8 pad mask

// ---------------- kernel 0: canonicalize pad mask (dtype-robust) ----------------
// The harness supports {float32,int32,bfloat16}; a bool input is most likely
// serialized as int32. Detect the encoding from the data itself, scanning only
// the first n BYTES (safe under every dtype hypothesis), then canonicalize.
__global__ void pad_canon_kernel(const unsigned char* __restrict__ praw, int n) {
    __shared__ int flags;  // bit0: some word not in {0,1}; bit1: some word not in {0,1.0f}
    if (threadIdx.x == 0) flags = 0;
    __syncthreads();
    const unsigned int* w = (const unsigned int*)praw;
    int nwords_safe = n >> 2;              // n bytes is the minimum allocation size
    int f = 0;
    for (int i = threadIdx.x; i < nwords_safe; i += blockDim.x) {
        unsigned int x = w[i];
        if (x > 1u) f |= 1;
        if (x != 0u && x != 0x3F800000u) f |= 2;
    }
    atomicOr(&flags, f);
    __syncthreads();
    int fl = flags;
    // mode: 1 = 4-byte words (int32), 2 = 4-byte words (float32), 0 = 1-byte
    int mode = ((fl & 1) == 0) ? 1 : (((fl & 2) == 0) ? 2 : 0);
    if (mode == 0) {
        for (int i = threadIdx.x; i < n; i += blockDim.x) g_pad[i] = praw[i] ? 1 : 0;
    } else {
        for (int i = threadIdx.x; i < n; i += blockDim.x) g_pad[i] = w[i] ? 1 : 0;
    }
}

// ---------------- kernel 1: closed-form museformer mask ----------------
__global__ void mask_kernel(const int* __restrict__ sp, int NB) {
    __shared__ int ssp[256];
    for (int t = threadIdx.x; t < NB; t += blockDim.x) ssp[t] = sp[t];
    __syncthreads();

    int i = blockIdx.x;
    // c = number of summaries at positions < i
    int lo = 0, hi = NB;
    while (lo < hi) { int mid = (lo + hi) >> 1; if (ssp[mid] < i) lo = mid + 1; else hi = mid; }
    int c = lo;
    bool is_sum = (c < NB) && (ssp[c] == i);

    int w = threadIdx.x;          // word index 0..63
    int jbase = w * 32;
    unsigned bits = 0;

    if (is_sum) {
        int rlo = (c == 0) ? 1 : ssp[c - 1] + 1;
        #pragma unroll
        for (int jj = 0; jj < 32; ++jj) {
            int j = jbase + jj;
            if (j >= rlo && j < i) bits |= (1u << jj);
        }
    } else {
        bool aliasOk = (i + 1 < S_LEN) && !((c < NB) && (ssp[c] == i + 1));
        if (c == 0) {
            #pragma unroll
            for (int jj = 0; jj < 32; ++jj) {
                int j = jbase + jj;
                bool b = (j <= i) || (aliasOk && (j == i + 1));
                if (b) bits |= (1u << jj);
            }
        } else {
            int f = ssp[c - 1] + 1;
            const int SB[6] = {1, 2, 4, 8, 16, 32};
            int pt[6], lo6[6], hi6[6];
            #pragma unroll
            for (int t = 0; t < 6; ++t) {
                int s = SB[t];
                pt[t]  = (c >= s) ? ssp[c - s] : -1;
                if (c > s) { lo6[t] = ssp[c - s - 1]; hi6[t] = ssp[c - s] - 1; }
                else       { lo6[t] = 0; hi6[t] = -1; }
            }
            #pragma unroll
            for (int jj = 0; jj < 32; ++jj) {
                int j = jbase + jj;
                bool b = (i > f) && (j >= f + 1) && (j <= i);
                #pragma unroll
                for (int t = 0; t < 6; ++t) {
                    b |= (j == pt[t]);
                    b |= (j > lo6[t]) && (j < hi6[t]);
                }
                b |= aliasOk && (j == i + 1);
                if (b) bits |= (1u << jj);
            }
        }
    }
    g_mask[i][w] = bits;
}

// ---------------- kernel 2: 64x64 tile occupancy bitmap ----------------
__global__ void occ_kernel() {
    int qt = blockIdx.x;
    int kt = threadIdx.x;          // 32 threads = 1 warp
    unsigned acc = 0;
    for (int r = 0; r < BM; ++r)
        acc |= g_mask[qt * BM + r][kt * 2] | g_mask[qt * BM + r][kt * 2 + 1];
    unsigned ball = __ballot_sync(0xffffffffu, acc != 0u);
    if (kt == 0) g_occ[qt] = ball;
}

// ---------------- kernel 3: per-(b,h) mean of V (empty-row fallback) ----------------
__global__ void vmean_kernel(const float* __restrict__ v) {
    __shared__ float part[4][HD];
    int bh = blockIdx.x;
    int d = threadIdx.x & 63, g = threadIdx.x >> 6;     // 256 threads: 4 s-groups x 64 d
    const float* p = v + (size_t)bh * S_LEN * HD + (size_t)(g * (S_LEN / 4)) * HD + d;
    float s0 = 0.f, s1 = 0.f, s2 = 0.f, s3 = 0.f;
    for (int i = 0; i < S_LEN / 4; i += 4) {
        s0 += p[(i + 0) * HD]; s1 += p[(i + 1) * HD];
        s2 += p[(i + 2) * HD]; s3 += p[(i + 3) * HD];
    }
    part[g][d] = (s0 + s1) + (s2 + s3);
    __syncthreads();
    if (g == 0)
        g_vmean[bh][d] = (part[0][d] + part[1][d] + part[2][d] + part[3][d]) * (1.0f / S_LEN);
}

// ---------------- kernel 4: sparse flash attention (fp32) ----------------
__global__ __launch_bounds__(NTHREADS)
void attn_kernel(const float* __restrict__ q, const float* __restrict__ k,
                 const float* __restrict__ v, float* __restrict__ out) {
    extern __shared__ float smem[];
    float* Qs = smem;                       // [64][64]
    float* Ks = Qs + BM * HD;               // [64][65]  (aliased by P after GEMM1)
    float* Vs = Ks + BN * KSTRIDE;          // [64][64]
    float* Ps = Ks;

    const int qt = blockIdx.x;
    const int bh = blockIdx.y;
    const int b  = bh >> 3;                 // H = 8
    const int tid = threadIdx.x;
    const int tx = tid & 15;                // 16 col-groups of 4
    const int ty = tid >> 4;                // 8 row-groups of 8

    const size_t base = (size_t)bh * S_LEN * HD;

    // load Q tile (contiguous 16 KB)
    {
        const float4* qg = (const float4*)(q + base + (size_t)qt * BM * HD);
        float4* qs4 = (float4*)Qs;
        #pragma unroll
        for (int idx = tid; idx < BM * HD / 4; idx += NTHREADS) qs4[idx] = qg[idx];
    }

    float m[8], l[8], acc[8][4];
    #pragma unroll
    for (int rr = 0; rr < 8; ++rr) {
        m[rr] = -CUDART_INF_F; l[rr] = 0.f;
        #pragma unroll
        for (int cc = 0; cc < 4; ++cc) acc[rr][cc] = 0.f;
    }

    unsigned char padq[8];
    #pragma unroll
    for (int rr = 0; rr < 8; ++rr)
        padq[rr] = g_pad[b * S_LEN + qt * BM + ty * 8 + rr];

    const float scale = 0.125f;             // 1/sqrt(64)
    const unsigned occ = g_occ[qt];
    __syncthreads();                        // Q tile visible

    for (int kt = 0; kt < NKT; ++kt) {
        if (!((occ >> kt) & 1u)) continue;

        // load K (stride-65) and V (stride-64) tiles
        const float* kg = k + base + (size_t)kt * BN * HD;
        for (int idx = tid; idx < BN * HD; idx += NTHREADS) {
            int r = idx >> 6, d0 = idx & 63;
            Ks[r * KSTRIDE + d0] = kg[idx];
        }
        {
            const float4* vg4 = (const float4*)(v + base + (size_t)kt * BN * HD);
            float4* vs4 = (float4*)Vs;
            #pragma unroll
            for (int idx = tid; idx < BN * HD / 4; idx += NTHREADS) vs4[idx] = vg4[idx];
        }
        __syncthreads();

        // ---- GEMM1: S = Q K^T (8x4 per thread) ----
        float sacc[8][4];
        #pragma unroll
        for (int rr = 0; rr < 8; ++rr)
            #pragma unroll
            for (int cc = 0; cc < 4; ++cc) sacc[rr][cc] = 0.f;

        #pragma unroll 4
        for (int kk = 0; kk < HD; ++kk) {
            float qv[8], kv[4];
            #pragma unroll
            for (int rr = 0; rr < 8; ++rr) qv[rr] = Qs[(ty * 8 + rr) * HD + kk];
            #pragma unroll
            for (int cc = 0; cc < 4; ++cc) kv[cc] = Ks[(tx * 4 + cc) * KSTRIDE + kk];
            #pragma unroll
            for (int rr = 0; rr < 8; ++rr)
                #pragma unroll
                for (int cc = 0; cc < 4; ++cc)
                    sacc[rr][cc] = fmaf(qv[rr], kv[cc], sacc[rr][cc]);
        }

        // ---- mask + online softmax ----
        uchar4 pk = *(const uchar4*)(g_pad + b * S_LEN + kt * BN + tx * 4);
        unsigned char pkc[4] = {pk.x, pk.y, pk.z, pk.w};

        float tmax[8];
        #pragma unroll
        for (int rr = 0; rr < 8; ++rr) {
            unsigned mw = g_mask[qt * BM + ty * 8 + rr][kt * 2 + (tx >> 3)];
            bool rowok = padq[rr] != 0;
            float tm = -CUDART_INF_F;
            #pragma unroll
            for (int cc = 0; cc < 4; ++cc) {
                bool ok = rowok && (((mw >> ((tx * 4 + cc) & 31)) & 1u) != 0u) && (pkc[cc] != 0);
                sacc[rr][cc] = ok ? sacc[rr][cc] * scale : -CUDART_INF_F;
                tm = fmaxf(tm, sacc[rr][cc]);
            }
            tmax[rr] = tm;
        }
        #pragma unroll
        for (int rr = 0; rr < 8; ++rr) {
            #pragma unroll
            for (int off = 8; off >= 1; off >>= 1)
                tmax[rr] = fmaxf(tmax[rr], __shfl_xor_sync(0xffffffffu, tmax[rr], off, 16));
        }

        float alpha[8];
        #pragma unroll
        for (int rr = 0; rr < 8; ++rr) {
            float mn = fmaxf(m[rr], tmax[rr]);
            alpha[rr] = (mn == -CUDART_INF_F) ? 1.0f : __expf(m[rr] - mn);
            m[rr] = mn;
        }
        #pragma unroll
        for (int rr = 0; rr < 8; ++rr) {
            float rs = 0.f;
            #pragma unroll
            for (int cc = 0; cc < 4; ++cc) {
                float p = (sacc[rr][cc] > -CUDART_INF_F) ? __expf(sacc[rr][cc] - m[rr]) : 0.f;
                sacc[rr][cc] = p;
                rs += p;
            }
            #pragma unroll
            for (int off = 8; off >= 1; off >>= 1)
                rs += __shfl_xor_sync(0xffffffffu, rs, off, 16);
            l[rr] = l[rr] * alpha[rr] + rs;
            #pragma unroll
            for (int cc = 0; cc < 4; ++cc) acc[rr][cc] *= alpha[rr];
        }

        // ---- stage P to shared (aliases K region) ----
        __syncthreads();   // all K reads done
        #pragma unroll
        for (int rr = 0; rr < 8; ++rr)
            #pragma unroll
            for (int cc = 0; cc < 4; ++cc)
                Ps[(ty * 8 + rr) * KSTRIDE + tx * 4 + cc] = sacc[rr][cc];
        __syncthreads();

        // ---- GEMM2: O += P V ----
        #pragma unroll 2
        for (int kk = 0; kk < BN; ++kk) {
            float pv[8];
            #pragma unroll
            for (int rr = 0; rr < 8; ++rr) pv[rr] = Ps[(ty * 8 + rr) * KSTRIDE + kk];
            float4 vvv = *(const float4*)(Vs + kk * HD + tx * 4);
            float vv[4] = {vvv.x, vvv.y, vvv.z, vvv.w};
            #pragma unroll
            for (int rr = 0; rr < 8; ++rr)
                #pragma unroll
                for (int cc = 0; cc < 4; ++cc)
                    acc[rr][cc] = fmaf(pv[rr], vv[cc], acc[rr][cc]);
        }
        __syncthreads();   // before next tile overwrites Ks/Vs
    }

    // ---- epilogue ----
    #pragma unroll
    for (int rr = 0; rr < 8; ++rr) {
        float4 o;
        if (l[rr] > 0.f) {
            float inv = 1.0f / l[rr];
            o.x = acc[rr][0] * inv; o.y = acc[rr][1] * inv;
            o.z = acc[rr][2] * inv; o.w = acc[rr][3] * inv;
        } else {
            // fully-masked row: reference softmax over all -1e9 -> uniform -> mean(V)
            o.x = g_vmean[bh][tx * 4 + 0]; o.y = g_vmean[bh][tx * 4 + 1];
            o.z = g_vmean[bh][tx * 4 + 2]; o.w = g_vmean[bh][tx * 4 + 3];
        }
        *(float4*)(out + base + (size_t)(qt * BM + ty * 8 + rr) * HD + tx * 4) = o;
    }
}

// ---------------- launch ----------------
extern "C" void kernel_launch(void* const* d_in, const int* in_sizes, int n_in,
                              void* d_out, int out_size) {
    // size-based input identification (hedge against metadata reordering):
    // three ~4M tensors = q,k,v in order; 8192 elems = pad; remaining small = bars
    int big[3] = {0, 1, 2}; int nbig = 0; int ip = -1, ib = -1;
    for (int i = 0; i < n_in; ++i) {
        if (in_sizes[i] >= (1 << 20))            { if (nbig < 3) big[nbig++] = i; }
        else if (in_sizes[i] == BATCH * S_LEN)   ip = i;
        else                                     ib = i;
    }
    if (nbig != 3 || ip < 0 || ib < 0) { big[0] = 0; big[1] = 1; big[2] = 2; ip = 3; ib = 4; }

    const float* q = (const float*)d_in[big[0]];
    const float* k = (const float*)d_in[big[1]];
    const float* v = (const float*)d_in[big[2]];
    const unsigned char* praw = (const unsigned char*)d_in[ip];
    const int* sp = (const int*)d_in[ib];
    const int NB = in_sizes[ib];
    float* out = (float*)d_out;

    cudaFuncSetAttribute(attn_kernel, cudaFuncAttributeMaxDynamicSharedMemorySize, SMEM_BYTES);

    pad_canon_kernel<<<1, 1024>>>(praw, BATCH * S_LEN);
    mask_kernel<<<S_LEN, 64>>>(sp, NB);
    occ_kernel<<<NQT, 32>>>();
    vmean_kernel<<<BH, 256>>>(v);
    attn_kernel<<<dim3(NQT, BH), NTHREADS, SMEM_BYTES>>>(q, k, v, out);
}

// round 4
// speedup vs baseline: 1.1367x; 1.1367x over previous
#include <cuda_runtime.h>
#include <math_constants.h>

// Problem constants (fixed by setup_inputs)
#define S_LEN 2048
#define BATCH 4
#define HEADS 8
#define BH    (BATCH*HEADS)        // 32
#define HD    64
#define BM    64
#define BN    64
#define NQT   (S_LEN/BM)           // 32
#define NKT   (S_LEN/BN)           // 32
#define NTHREADS 128

#define KST   68                   // padded float stride for K / P tiles (16B-aligned rows)
#define SMEM_FLOATS (BM*HD + BN*KST + BN*HD)       // Q + K(=P alias) + V
#define SMEM_BYTES  (SMEM_FLOATS * 4)              // 50176

// ---------------- device scratch (no allocations allowed) ----------------
__device__ unsigned g_maskb[BATCH][S_LEN][S_LEN/32]; // 2 MB pad-folded museformer bitmask
__device__ unsigned g_occ[NQT];                      // per-q-tile k-tile occupancy (muse superset)
__device__ float    g_vmean[BH][HD];                 // fallback: mean of V over S

// ---------------- interval/point bit helpers ----------------
__device__ __forceinline__ unsigned rng_bits(int lo, int hi, int jbase) {
    // bits for j in [lo, hi) restricted to [jbase, jbase+32)
    int a = lo - jbase; a = a < 0 ? 0 : a;
    int b = hi - jbase; b = b > 32 ? 32 : b;
    if (b <= a) return 0u;
    unsigned mb = (b == 32) ? 0xffffffffu : ((1u << b) - 1u);
    unsigned ma = (1u << a) - 1u;   // a <= 31 here
    return mb & ~ma;
}
__device__ __forceinline__ unsigned pt_bit(int p, int jbase) {
    unsigned d = (unsigned)(p - jbase);
    return (d < 32u) ? (1u << d) : 0u;
}

// ---------------- fused prep kernel ----------------
// blocks 0..31   : per-q-tile mask (pad-folded, per batch) + occupancy
// blocks 32..95  : vmean (2 blocks per bh, 32 d-cols each)
__global__ __launch_bounds__(256)
void prep_kernel(const int* __restrict__ sp, int NB,
                 const unsigned char* __restrict__ praw,
                 const float* __restrict__ v) {
    __shared__ int      ssp[256];
    __shared__ unsigned pbits[BATCH * 64];   // 8192 pad bools as bits
    __shared__ unsigned socc[64];
    __shared__ int      flags;
    __shared__ float4   part4[32][8];

    const int tid = threadIdx.x;
    const int blk = blockIdx.x;

    if (blk < NQT) {
        // ===== mask + occ block =====
        const int qt = blk;
        if (tid == 0) flags = 0;
        for (int t = tid; t < NB && t < 256; t += 256) ssp[t] = sp[t];
        if (tid < 64) socc[tid] = 0u;
        __syncthreads();

        // pad dtype detection: scan first 8192 bytes as words (safe for all dtypes)
        const unsigned* w = (const unsigned*)praw;
        int f = 0;
        for (int i = tid; i < (BATCH * S_LEN) / 4; i += 256) {
            unsigned x = w[i];
            if (x > 1u) f |= 1;                          // not int32 {0,1}
            if (x != 0u && x != 0x3F800000u) f |= 2;     // not float32 {0,1.0}
        }
        if (f) atomicOr(&flags, f);
        __syncthreads();
        const int fl = flags;
        const int mode = ((fl & 1) == 0) ? 1 : (((fl & 2) == 0) ? 2 : 0); // 1/2: word, 0: byte

        // build pad bitmask: 256 words cover BATCH*S bools
        {
            unsigned bits = 0;
            if (mode == 0) {
                for (int j = 0; j < 32; ++j) if (praw[tid * 32 + j]) bits |= 1u << j;
            } else {
                for (int j = 0; j < 32; ++j) if (w[tid * 32 + j]) bits |= 1u << j;
            }
            pbits[tid] = bits;
        }
        __syncthreads();

        // 64 rows x 64 words = 4096 cells, 16 per thread
        for (int p = 0; p < 16; ++p) {
            int cell = tid + p * 256;
            int row = cell >> 6;
            int wdi = cell & 63;
            int i = qt * 64 + row;
            int jbase = wdi * 32;

            // c = #summaries at positions < i
            int lo = 0, hi = NB;
            while (lo < hi) { int mid = (lo + hi) >> 1; if (ssp[mid] < i) lo = mid + 1; else hi = mid; }
            int c = lo;
            bool is_sum = (c < NB) && (ssp[c] == i);

            unsigned bits;
            if (is_sum) {
                int rlo = (c == 0) ? 1 : ssp[c - 1] + 1;
                bits = rng_bits(rlo, i, jbase);
            } else {
                bool aliasOk = (i + 1 < S_LEN) && !((c < NB) && (ssp[c] == i + 1));
                if (c == 0) {
                    bits = rng_bits(0, i + 1, jbase);
                } else {
                    int fi = ssp[c - 1] + 1;
                    bits = (i > fi) ? rng_bits(fi + 1, i + 1, jbase) : 0u;
                    const int SB[6] = {1, 2, 4, 8, 16, 32};
                    #pragma unroll
                    for (int t6 = 0; t6 < 6; ++t6) {
                        int s = SB[t6];
                        if (c >= s) bits |= pt_bit(ssp[c - s], jbase);
                        if (c > s)  bits |= rng_bits(ssp[c - s - 1] + 1, ssp[c - s] - 1, jbase);
                    }
                }
                if (aliasOk) bits |= pt_bit(i + 1, jbase);
            }
            if (bits) atomicOr(&socc[wdi], bits);

            // fold pad (row & col) per batch and store
            #pragma unroll
            for (int b = 0; b < BATCH; ++b) {
                unsigned rowp = (pbits[(b * S_LEN + i) >> 5] >> (i & 31)) & 1u;
                g_maskb[b][i][wdi] = rowp ? (bits & pbits[b * 64 + wdi]) : 0u;
            }
        }
        __syncthreads();
        if (tid < 32) {
            unsigned ow = socc[2 * tid] | socc[2 * tid + 1];
            unsigned ball = __ballot_sync(0xffffffffu, ow != 0u);
            if (tid == 0) g_occ[qt] = ball;
        }
    } else {
        // ===== vmean block (2 per bh) =====
        const int q = blk - NQT;
        const int bh = q >> 1, half = q & 1;
        const int dgl = tid & 7;
        const int dg = half * 8 + dgl;       // float4 column 0..15
        const int rg = tid >> 3;             // 0..31, 64 rows each
        const float4* p = (const float4*)(v + (size_t)bh * S_LEN * HD) + dg;
        const int r0 = rg * 64;

        float4 a0 = {0,0,0,0}, a1 = {0,0,0,0}, a2 = {0,0,0,0}, a3 = {0,0,0,0};
        #pragma unroll 2
        for (int i = 0; i < 64; i += 8) {
            float4 x0 = p[(r0 + i + 0) * (HD/4)];
            float4 x1 = p[(r0 + i + 1) * (HD/4)];
            float4 x2 = p[(r0 + i + 2) * (HD/4)];
            float4 x3 = p[(r0 + i + 3) * (HD/4)];
            float4 x4 = p[(r0 + i + 4) * (HD/4)];
            float4 x5 = p[(r0 + i + 5) * (HD/4)];
            float4 x6 = p[(r0 + i + 6) * (HD/4)];
            float4 x7 = p[(r0 + i + 7) * (HD/4)];
            a0.x += x0.x + x4.x; a0.y += x0.y + x4.y; a0.z += x0.z + x4.z; a0.w += x0.w + x4.w;
            a1.x += x1.x + x5.x; a1.y += x1.y + x5.y; a1.z += x1.z + x5.z; a1.w += x1.w + x5.w;
            a2.x += x2.x + x6.x; a2.y += x2.y + x6.y; a2.z += x2.z + x6.z; a2.w += x2.w + x6.w;
            a3.x += x3.x + x7.x; a3.y += x3.y + x7.y; a3.z += x3.z + x7.z; a3.w += x3.w + x7.w;
        }
        float4 a;
        a.x = (a0.x + a1.x) + (a2.x + a3.x);
        a.y = (a0.y + a1.y) + (a2.y + a3.y);
        a.z = (a0.z + a1.z) + (a2.z + a3.z);
        a.w = (a0.w + a1.w) + (a2.w + a3.w);
        part4[rg][dgl] = a;
        __syncthreads();
        #pragma unroll
        for (int s = 16; s >= 1; s >>= 1) {
            if (rg < s) {
                float4 o = part4[rg][dgl], x = part4[rg + s][dgl];
                o.x += x.x; o.y += x.y; o.z += x.z; o.w += x.w;
                part4[rg][dgl] = o;
            }
            __syncthreads();
        }
        if (rg == 0) {
            float4 a4 = part4[0][dgl];
            const float inv = 1.0f / (float)S_LEN;
            g_vmean[bh][dg * 4 + 0] = a4.x * inv;
            g_vmean[bh][dg * 4 + 1] = a4.y * inv;
            g_vmean[bh][dg * 4 + 2] = a4.z * inv;
            g_vmean[bh][dg * 4 + 3] = a4.w * inv;
        }
    }
}

// ---------------- sparse flash attention (fp32, vectorized smem) ----------------
// thread (tx 0..15, ty 0..7): rows ty*8+rr, GEMM1 k-cols cc*16+tx, GEMM2 d-cols tx*4+cc
__global__ __launch_bounds__(NTHREADS, 3)
void attn_kernel(const float* __restrict__ q, const float* __restrict__ k,
                 const float* __restrict__ v, float* __restrict__ out) {
    extern __shared__ float smem[];
    float* Qs = smem;                       // [64][64]
    float* Ks = Qs + BM * HD;               // [64][68]  (aliased by P after GEMM1)
    float* Vs = Ks + BN * KST;              // [64][64]
    float* Ps = Ks;
    __shared__ unsigned mask_sh[BM * 2];    // [row][2] mask words for current k-tile

    const int qt = blockIdx.x;
    const int bh = blockIdx.y;
    const int b  = bh >> 3;                 // H = 8
    const int tid = threadIdx.x;
    const int tx = tid & 15;
    const int ty = tid >> 4;

    const size_t base = (size_t)bh * S_LEN * HD;

    // load Q tile (contiguous 16 KB)
    {
        const float4* qg = (const float4*)(q + base + (size_t)qt * BM * HD);
        float4* qs4 = (float4*)Qs;
        #pragma unroll
        for (int idx = tid; idx < BM * HD / 4; idx += NTHREADS) qs4[idx] = qg[idx];
    }

    float m[8], l[8];
    float4 acc4[8];
    #pragma unroll
    for (int rr = 0; rr < 8; ++rr) {
        m[rr] = -CUDART_INF_F; l[rr] = 0.f;
        acc4[rr] = make_float4(0.f, 0.f, 0.f, 0.f);
    }

    const float scale = 0.125f;             // 1/sqrt(64)
    const unsigned occ = g_occ[qt];
    __syncthreads();

    for (int kt = 0; kt < NKT; ++kt) {
        if (!((occ >> kt) & 1u)) continue;

        // ---- stage K (stride 68), V (stride 64), mask words ----
        {
            const float4* kg4 = (const float4*)(k + base + (size_t)kt * BN * HD);
            #pragma unroll
            for (int n = tid; n < BN * HD / 4; n += NTHREADS) {
                int kr = n >> 4, d4 = n & 15;
                *(float4*)(Ks + kr * KST + d4 * 4) = kg4[n];
            }
            const float4* vg4 = (const float4*)(v + base + (size_t)kt * BN * HD);
            float4* vs4 = (float4*)Vs;
            #pragma unroll
            for (int n = tid; n < BN * HD / 4; n += NTHREADS) vs4[n] = vg4[n];
        }
        if (tid < BM * 2)
            mask_sh[tid] = g_maskb[b][qt * 64 + (tid >> 1)][kt * 2 + (tid & 1)];
        __syncthreads();

        // ---- GEMM1: S = Q K^T  (float4 on both operands) ----
        float sacc[8][4];
        #pragma unroll
        for (int rr = 0; rr < 8; ++rr)
            #pragma unroll
            for (int cc = 0; cc < 4; ++cc) sacc[rr][cc] = 0.f;

        #pragma unroll 4
        for (int d4 = 0; d4 < HD / 4; ++d4) {
            float4 kv[4];
            #pragma unroll
            for (int cc = 0; cc < 4; ++cc)
                kv[cc] = *(const float4*)(Ks + (cc * 16 + tx) * KST + d4 * 4);
            #pragma unroll
            for (int rr = 0; rr < 8; ++rr) {
                float4 qv = *(const float4*)(Qs + (ty * 8 + rr) * HD + d4 * 4);
                #pragma unroll
                for (int cc = 0; cc < 4; ++cc) {
                    sacc[rr][cc] = fmaf(qv.x, kv[cc].x, sacc[rr][cc]);
                    sacc[rr][cc] = fmaf(qv.y, kv[cc].y, sacc[rr][cc]);
                    sacc[rr][cc] = fmaf(qv.z, kv[cc].z, sacc[rr][cc]);
                    sacc[rr][cc] = fmaf(qv.w, kv[cc].w, sacc[rr][cc]);
                }
            }
        }

        // ---- mask + online softmax (row spread over 16 tx lanes) ----
        float tmax[8];
        #pragma unroll
        for (int rr = 0; rr < 8; ++rr) {
            unsigned w0 = mask_sh[(ty * 8 + rr) * 2 + 0];
            unsigned w1 = mask_sh[(ty * 8 + rr) * 2 + 1];
            float tm = -CUDART_INF_F;
            #pragma unroll
            for (int cc = 0; cc < 4; ++cc) {
                unsigned wsel = (cc >= 2) ? w1 : w0;
                bool ok = ((wsel >> (((cc & 1) << 4) + tx)) & 1u) != 0u;
                sacc[rr][cc] = ok ? sacc[rr][cc] * scale : -CUDART_INF_F;
                tm = fmaxf(tm, sacc[rr][cc]);
            }
            tmax[rr] = tm;
        }
        #pragma unroll
        for (int rr = 0; rr < 8; ++rr) {
            #pragma unroll
            for (int off = 8; off >= 1; off >>= 1)
                tmax[rr] = fmaxf(tmax[rr], __shfl_xor_sync(0xffffffffu, tmax[rr], off, 16));
        }

        #pragma unroll
        for (int rr = 0; rr < 8; ++rr) {
            float mn = fmaxf(m[rr], tmax[rr]);
            float alpha = (mn == -CUDART_INF_F) ? 1.0f : __expf(m[rr] - mn);
            m[rr] = mn;
            float rs = 0.f;
            #pragma unroll
            for (int cc = 0; cc < 4; ++cc) {
                float pv = (sacc[rr][cc] > -CUDART_INF_F) ? __expf(sacc[rr][cc] - m[rr]) : 0.f;
                sacc[rr][cc] = pv;
                rs += pv;
            }
            #pragma unroll
            for (int off = 8; off >= 1; off >>= 1)
                rs += __shfl_xor_sync(0xffffffffu, rs, off, 16);
            l[rr] = l[rr] * alpha + rs;
            acc4[rr].x *= alpha; acc4[rr].y *= alpha; acc4[rr].z *= alpha; acc4[rr].w *= alpha;
        }

        // ---- stage P (aliases K region, same KST stride) ----
        __syncthreads();   // all K reads done
        #pragma unroll
        for (int rr = 0; rr < 8; ++rr)
            #pragma unroll
            for (int cc = 0; cc < 4; ++cc)
                Ps[(ty * 8 + rr) * KST + cc * 16 + tx] = sacc[rr][cc];
        __syncthreads();

        // ---- GEMM2: O += P V  (float4 on both operands) ----
        #pragma unroll 4
        for (int k4 = 0; k4 < BN / 4; ++k4) {
            float4 vv[4];
            #pragma unroll
            for (int j = 0; j < 4; ++j)
                vv[j] = *(const float4*)(Vs + (k4 * 4 + j) * HD + tx * 4);
            #pragma unroll
            for (int rr = 0; rr < 8; ++rr) {
                float4 pv = *(const float4*)(Ps + (ty * 8 + rr) * KST + k4 * 4);
                acc4[rr].x = fmaf(pv.x, vv[0].x, acc4[rr].x);
                acc4[rr].y = fmaf(pv.x, vv[0].y, acc4[rr].y);
                acc4[rr].z = fmaf(pv.x, vv[0].z, acc4[rr].z);
                acc4[rr].w = fmaf(pv.x, vv[0].w, acc4[rr].w);
                acc4[rr].x = fmaf(pv.y, vv[1].x, acc4[rr].x);
                acc4[rr].y = fmaf(pv.y, vv[1].y, acc4[rr].y);
                acc4[rr].z = fmaf(pv.y, vv[1].z, acc4[rr].z);
                acc4[rr].w = fmaf(pv.y, vv[1].w, acc4[rr].w);
                acc4[rr].x = fmaf(pv.z, vv[2].x, acc4[rr].x);
                acc4[rr].y = fmaf(pv.z, vv[2].y, acc4[rr].y);
                acc4[rr].z = fmaf(pv.z, vv[2].z, acc4[rr].z);
                acc4[rr].w = fmaf(pv.z, vv[2].w, acc4[rr].w);
                acc4[rr].x = fmaf(pv.w, vv[3].x, acc4[rr].x);
                acc4[rr].y = fmaf(pv.w, vv[3].y, acc4[rr].y);
                acc4[rr].z = fmaf(pv.w, vv[3].z, acc4[rr].z);
                acc4[rr].w = fmaf(pv.w, vv[3].w, acc4[rr].w);
            }
        }
        __syncthreads();   // before next tile overwrites Ks/Vs
    }

    // ---- epilogue ----
    #pragma unroll
    for (int rr = 0; rr < 8; ++rr) {
        float4 o;
        if (l[rr] > 0.f) {
            float inv = 1.0f / l[rr];
            o.x = acc4[rr].x * inv; o.y = acc4[rr].y * inv;
            o.z = acc4[rr].z * inv; o.w = acc4[rr].w * inv;
        } else {
            // fully-masked / padded row: softmax over constant row -> uniform -> mean(V)
            o.x = g_vmean[bh][tx * 4 + 0]; o.y = g_vmean[bh][tx * 4 + 1];
            o.z = g_vmean[bh][tx * 4 + 2]; o.w = g_vmean[bh][tx * 4 + 3];
        }
        *(float4*)(out + base + (size_t)(qt * BM + ty * 8 + rr) * HD + tx * 4) = o;
    }
}

// ---------------- launch ----------------
extern "C" void kernel_launch(void* const* d_in, const int* in_sizes, int n_in,
                              void* d_out, int out_size) {
    // size-based input identification (hedge against metadata reordering)
    int big[3] = {0, 1, 2}; int nbig = 0; int ip = -1, ib = -1;
    for (int i = 0; i < n_in; ++i) {
        if (in_sizes[i] >= (1 << 20))            { if (nbig < 3) big[nbig++] = i; }
        else if (in_sizes[i] == BATCH * S_LEN)   ip = i;
        else                                     ib = i;
    }
    if (nbig != 3 || ip < 0 || ib < 0) { big[0] = 0; big[1] = 1; big[2] = 2; ip = 3; ib = 4; }

    const float* q = (const float*)d_in[big[0]];
    const float* k = (const float*)d_in[big[1]];
    const float* v = (const float*)d_in[big[2]];
    const unsigned char* praw = (const unsigned char*)d_in[ip];
    const int* sp = (const int*)d_in[ib];
    const int NB = in_sizes[ib];
    float* out = (float*)d_out;

    cudaFuncSetAttribute(attn_kernel, cudaFuncAttributeMaxDynamicSharedMemorySize, SMEM_BYTES);

    prep_kernel<<<NQT + 2 * BH, 256>>>(sp, NB, praw, v);
    attn_kernel<<<dim3(NQT, BH), NTHREADS, SMEM_BYTES>>>(q, k, v, out);
}

// round 6
// speedup vs baseline: 1.4889x; 1.3098x over previous
#include <cuda_runtime.h>
#include <cuda_bf16.h>
#include <math_constants.h>
#include <cstdint>

// Problem constants (fixed by setup_inputs)
#define S_LEN 2048
#define BATCH 4
#define HEADS 8
#define BH    (BATCH*HEADS)        // 32
#define HD    64
#define BM    64                   // q rows per CTA
#define BN    64                   // k cols per tile
#define NQT   (S_LEN/BM)           // 32
#define NKT   (S_LEN/BN)           // 32

// ---------------- device scratch ----------------
__device__ unsigned g_mask[S_LEN][S_LEN/32];  // 512 KB museformer bitmask (no pad fold)
__device__ unsigned g_occ64[NQT];             // per-64-row-tile k-tile occupancy
__device__ unsigned g_padw[BATCH][S_LEN/32];  // pad bools as bits
__device__ float    g_vmean[BH][HD];          // fallback: mean of V over S

// ---------------- helpers ----------------
__device__ __forceinline__ unsigned rng_bits(int lo, int hi, int jbase) {
    int a = lo - jbase; a = a < 0 ? 0 : a;
    int b = hi - jbase; b = b > 32 ? 32 : b;
    if (b <= a) return 0u;
    unsigned mb = (b == 32) ? 0xffffffffu : ((1u << b) - 1u);
    unsigned ma = (1u << a) - 1u;
    return mb & ~ma;
}
__device__ __forceinline__ unsigned pt_bit(int p, int jbase) {
    unsigned d = (unsigned)(p - jbase);
    return (d < 32u) ? (1u << d) : 0u;
}

// fp32 pair -> packed bf16x2 hi + lo (residual) words; a = low half (lower k index)
__device__ __forceinline__ void split2(float a, float b, uint32_t& hi, uint32_t& lo) {
    __nv_bfloat16 ha = __float2bfloat16_rn(a);
    __nv_bfloat16 hb = __float2bfloat16_rn(b);
    float ra = a - __bfloat162float(ha);
    float rb = b - __bfloat162float(hb);
    __nv_bfloat16 la = __float2bfloat16_rn(ra);
    __nv_bfloat16 lb = __float2bfloat16_rn(rb);
    hi = ((uint32_t)__bfloat16_as_ushort(hb) << 16) | (uint32_t)__bfloat16_as_ushort(ha);
    lo = ((uint32_t)__bfloat16_as_ushort(lb) << 16) | (uint32_t)__bfloat16_as_ushort(la);
}

// m16n8k16 bf16 MMA, C += A*B  (standard PTX, no sm_103a-only features)
#define MMA(c, a, b0, b1) \
    asm volatile("mma.sync.aligned.m16n8k16.row.col.f32.bf16.bf16.f32 " \
        "{%0,%1,%2,%3}, {%4,%5,%6,%7}, {%8,%9}, {%0,%1,%2,%3};" \
        : "+f"((c)[0]), "+f"((c)[1]), "+f"((c)[2]), "+f"((c)[3]) \
        : "r"((a)[0]), "r"((a)[1]), "r"((a)[2]), "r"((a)[3]), "r"(b0), "r"(b1))

// ---------------- fused prep kernel ----------------
// blocks 0..31 : museformer mask (64 rows each) + occupancy
// blocks 32..95: vmean (2 per bh)
// block  96    : pad-mask dtype detection + bit pack
__global__ __launch_bounds__(256)
void prep_kernel(const int* __restrict__ sp, int NB,
                 const unsigned char* __restrict__ praw,
                 const float* __restrict__ v) {
    __shared__ int      ssp[256];
    __shared__ unsigned socc[64];
    __shared__ int      flags;
    __shared__ float4   part4[32][8];

    const int tid = threadIdx.x;
    const int blk = blockIdx.x;

    if (blk < NQT) {
        const int qt = blk;
        for (int t = tid; t < NB && t < 256; t += 256) ssp[t] = sp[t];
        if (tid < 64) socc[tid] = 0u;
        __syncthreads();

        for (int p = 0; p < 16; ++p) {
            int cell = tid + p * 256;
            int row = cell >> 6;
            int wdi = cell & 63;
            int i = qt * 64 + row;
            int jbase = wdi * 32;

            int lo = 0, hi = NB;
            while (lo < hi) { int mid = (lo + hi) >> 1; if (ssp[mid] < i) lo = mid + 1; else hi = mid; }
            int c = lo;
            bool is_sum = (c < NB) && (ssp[c] == i);

            unsigned bits;
            if (is_sum) {
                int rlo = (c == 0) ? 1 : ssp[c - 1] + 1;
                bits = rng_bits(rlo, i, jbase);
            } else {
                bool aliasOk = (i + 1 < S_LEN) && !((c < NB) && (ssp[c] == i + 1));
                if (c == 0) {
                    bits = rng_bits(0, i + 1, jbase);
                } else {
                    int fi = ssp[c - 1] + 1;
                    bits = (i > fi) ? rng_bits(fi + 1, i + 1, jbase) : 0u;
                    const int SB[6] = {1, 2, 4, 8, 16, 32};
                    #pragma unroll
                    for (int t6 = 0; t6 < 6; ++t6) {
                        int s = SB[t6];
                        if (c >= s) bits |= pt_bit(ssp[c - s], jbase);
                        if (c > s)  bits |= rng_bits(ssp[c - s - 1] + 1, ssp[c - s] - 1, jbase);
                    }
                }
                if (aliasOk) bits |= pt_bit(i + 1, jbase);
            }
            g_mask[i][wdi] = bits;
            if (bits) atomicOr(&socc[wdi], bits);
        }
        __syncthreads();
        if (tid < 32) {
            unsigned ow = socc[2 * tid] | socc[2 * tid + 1];
            unsigned ball = __ballot_sync(0xffffffffu, ow != 0u);
            if (tid == 0) g_occ64[qt] = ball;
        }
    } else if (blk < NQT + 2 * BH) {
        // ===== vmean =====
        const int q = blk - NQT;
        const int bh = q >> 1, half = q & 1;
        const int dgl = tid & 7;
        const int dg = half * 8 + dgl;
        const int rg = tid >> 3;
        const float4* p = (const float4*)(v + (size_t)bh * S_LEN * HD) + dg;
        const int r0 = rg * 64;

        float4 a0 = {0,0,0,0}, a1 = {0,0,0,0}, a2 = {0,0,0,0}, a3 = {0,0,0,0};
        #pragma unroll 2
        for (int i = 0; i < 64; i += 8) {
            float4 x0 = p[(r0 + i + 0) * (HD/4)];
            float4 x1 = p[(r0 + i + 1) * (HD/4)];
            float4 x2 = p[(r0 + i + 2) * (HD/4)];
            float4 x3 = p[(r0 + i + 3) * (HD/4)];
            float4 x4 = p[(r0 + i + 4) * (HD/4)];
            float4 x5 = p[(r0 + i + 5) * (HD/4)];
            float4 x6 = p[(r0 + i + 6) * (HD/4)];
            float4 x7 = p[(r0 + i + 7) * (HD/4)];
            a0.x += x0.x + x4.x; a0.y += x0.y + x4.y; a0.z += x0.z + x4.z; a0.w += x0.w + x4.w;
            a1.x += x1.x + x5.x; a1.y += x1.y + x5.y; a1.z += x1.z + x5.z; a1.w += x1.w + x5.w;
            a2.x += x2.x + x6.x; a2.y += x2.y + x6.y; a2.z += x2.z + x6.z; a2.w += x2.w + x6.w;
            a3.x += x3.x + x7.x; a3.y += x3.y + x7.y; a3.z += x3.z + x7.z; a3.w += x3.w + x7.w;
        }
        float4 a;
        a.x = (a0.x + a1.x) + (a2.x + a3.x);
        a.y = (a0.y + a1.y) + (a2.y + a3.y);
        a.z = (a0.z + a1.z) + (a2.z + a3.z);
        a.w = (a0.w + a1.w) + (a2.w + a3.w);
        part4[rg][dgl] = a;
        __syncthreads();
        #pragma unroll
        for (int s = 16; s >= 1; s >>= 1) {
            if (rg < s) {
                float4 o = part4[rg][dgl], x = part4[rg + s][dgl];
                o.x += x.x; o.y += x.y; o.z += x.z; o.w += x.w;
                part4[rg][dgl] = o;
            }
            __syncthreads();
        }
        if (rg == 0) {
            float4 a4 = part4[0][dgl];
            const float inv = 1.0f / (float)S_LEN;
            g_vmean[bh][dg * 4 + 0] = a4.x * inv;
            g_vmean[bh][dg * 4 + 1] = a4.y * inv;
            g_vmean[bh][dg * 4 + 2] = a4.z * inv;
            g_vmean[bh][dg * 4 + 3] = a4.w * inv;
        }
    } else {
        // ===== pad canon =====
        if (tid == 0) flags = 0;
        __syncthreads();
        const unsigned* w = (const unsigned*)praw;
        int f = 0;
        for (int i = tid; i < (BATCH * S_LEN) / 4; i += 256) {
            unsigned x = w[i];
            if (x > 1u) f |= 1;
            if (x != 0u && x != 0x3F800000u) f |= 2;
        }
        if (f) atomicOr(&flags, f);
        __syncthreads();
        const int fl = flags;
        const int mode = ((fl & 1) == 0) ? 1 : (((fl & 2) == 0) ? 2 : 0);
        unsigned bits = 0;
        if (mode == 0) { for (int j = 0; j < 32; ++j) if (praw[tid * 32 + j]) bits |= 1u << j; }
        else           { for (int j = 0; j < 32; ++j) if (w[tid * 32 + j])    bits |= 1u << j; }
        ((unsigned*)g_padw)[tid] = bits;
    }
}

// ---------------- sparse flash attention: bf16 hi/lo 3-pass mma.sync ----------------
// 4 warps; warp w owns rows w*16..w*16+15 of the 64-row q-tile.
// lane: g = lane>>2 (row group), lq = lane&3.
// smem B layouts (stride 65 words): K word[d/2][n]=pack(K[n][d],K[n][d+1]);
//                                   V word[s/2][d]=pack(V[s][d],V[s+1][d]).
#define BSTRIDE 65
__global__ __launch_bounds__(128)
void attn_kernel(const float* __restrict__ q, const float* __restrict__ k,
                 const float* __restrict__ v, float* __restrict__ out) {
    __shared__ uint32_t Khi[32 * BSTRIDE], Klo[32 * BSTRIDE];
    __shared__ uint32_t Vhi[32 * BSTRIDE], Vlo[32 * BSTRIDE];
    __shared__ unsigned mask_sh[BM * 2];

    const int qt  = blockIdx.x;
    const int bh  = blockIdx.y;
    const int b   = bh >> 3;
    const int tid = threadIdx.x;
    const int w   = tid >> 5;
    const int lane = tid & 31;
    const int g   = lane >> 2;
    const int lq  = lane & 3;

    const size_t base = (size_t)bh * S_LEN * HD;

    // ---- preload Q fragments (scale folded), hi/lo ----
    uint32_t Qh[4][4], Ql[4][4];
    {
        const float sc = 0.125f;
        const float* qr0 = q + base + (size_t)(qt * BM + w * 16 + g) * HD;
        const float* qr1 = qr0 + 8 * HD;
        #pragma unroll
        for (int kk = 0; kk < 4; ++kk) {
            int d0 = kk * 16 + 2 * lq;
            float2 x0 = *(const float2*)(qr0 + d0);
            float2 x1 = *(const float2*)(qr1 + d0);
            float2 x2 = *(const float2*)(qr0 + d0 + 8);
            float2 x3 = *(const float2*)(qr1 + d0 + 8);
            split2(x0.x * sc, x0.y * sc, Qh[kk][0], Ql[kk][0]);
            split2(x1.x * sc, x1.y * sc, Qh[kk][1], Ql[kk][1]);
            split2(x2.x * sc, x2.y * sc, Qh[kk][2], Ql[kk][2]);
            split2(x3.x * sc, x3.y * sc, Qh[kk][3], Ql[kk][3]);
        }
    }

    float oacc[8][4];
    #pragma unroll
    for (int j = 0; j < 8; ++j)
        #pragma unroll
        for (int c = 0; c < 4; ++c) oacc[j][c] = 0.f;
    float m0 = -CUDART_INF_F, m1 = -CUDART_INF_F, l0 = 0.f, l1 = 0.f;

    const unsigned occ = g_occ64[qt];

    #pragma unroll 1
    for (int kt = 0; kt < NKT; ++kt) {
        if (!((occ >> kt) & 1u)) continue;

        // ---- stage K tile: words [d/2][n], hi/lo ----
        {
            const int dc = tid & 15, n0 = tid >> 4;   // 8 rows per thread
            #pragma unroll
            for (int it = 0; it < 8; ++it) {
                int n = n0 + it * 8;
                float4 x = *(const float4*)(k + base + (size_t)(kt * BN + n) * HD + dc * 4);
                uint32_t h0, h1, q0, q1;
                split2(x.x, x.y, h0, q0);
                split2(x.z, x.w, h1, q1);
                int widx = (2 * dc) * BSTRIDE + n;
                Khi[widx] = h0; Khi[widx + BSTRIDE] = h1;
                Klo[widx] = q0; Klo[widx + BSTRIDE] = q1;
            }
        }
        // ---- stage V tile: words [s/2][d], hi/lo ----
        {
            const int dc = tid & 15, rp0 = tid >> 4;  // 4 row-pairs per thread
            #pragma unroll
            for (int it = 0; it < 4; ++it) {
                int rp = rp0 + it * 8;
                const float* vr = v + base + (size_t)(kt * BN + 2 * rp) * HD + dc * 4;
                float4 x = *(const float4*)(vr);
                float4 y = *(const float4*)(vr + HD);
                uint32_t h0, h1, h2, h3, q0, q1, q2, q3;
                split2(x.x, y.x, h0, q0);
                split2(x.y, y.y, h1, q1);
                split2(x.z, y.z, h2, q2);
                split2(x.w, y.w, h3, q3);
                int widx = rp * BSTRIDE + dc * 4;
                Vhi[widx + 0] = h0; Vhi[widx + 1] = h1; Vhi[widx + 2] = h2; Vhi[widx + 3] = h3;
                Vlo[widx + 0] = q0; Vlo[widx + 1] = q1; Vlo[widx + 2] = q2; Vlo[widx + 3] = q3;
            }
        }
        // ---- stage mask words (pad folded) ----
        {
            int rt = tid >> 1, h = tid & 1;
            int grow = qt * BM + rt;
            unsigned rowp = (g_padw[b][grow >> 5] >> (grow & 31)) & 1u;
            mask_sh[tid] = rowp ? (g_mask[grow][2 * kt + h] & g_padw[b][2 * kt + h]) : 0u;
        }
        __syncthreads();

        // ---- GEMM1: S = Q K^T (3-pass) ----
        float sacc[8][4];
        #pragma unroll
        for (int j = 0; j < 8; ++j)
            #pragma unroll
            for (int c = 0; c < 4; ++c) sacc[j][c] = 0.f;

        #pragma unroll
        for (int kk = 0; kk < 4; ++kk) {
            int bidx = (kk * 8 + lq) * BSTRIDE + g;
            #pragma unroll
            for (int j = 0; j < 8; ++j) {
                uint32_t bh0 = Khi[bidx + j * 8];
                uint32_t bh1 = Khi[bidx + j * 8 + 4 * BSTRIDE];
                uint32_t bl0 = Klo[bidx + j * 8];
                uint32_t bl1 = Klo[bidx + j * 8 + 4 * BSTRIDE];
                MMA(sacc[j], Qh[kk], bh0, bh1);
                MMA(sacc[j], Qh[kk], bl0, bl1);
                MMA(sacc[j], Ql[kk], bh0, bh1);
            }
        }

        // ---- masked online softmax (rows g and g+8 of warp block) ----
        unsigned r0w0 = mask_sh[(w * 16 + g) * 2],     r0w1 = mask_sh[(w * 16 + g) * 2 + 1];
        unsigned r1w0 = mask_sh[(w * 16 + g + 8) * 2], r1w1 = mask_sh[(w * 16 + g + 8) * 2 + 1];

        float tm0 = -CUDART_INF_F, tm1 = -CUDART_INF_F;
        #pragma unroll
        for (int j = 0; j < 8; ++j) {
            int c0 = j * 8 + 2 * lq;
            unsigned w0sel = (c0 & 32) ? r0w1 : r0w0;
            unsigned w1sel = (c0 & 32) ? r1w1 : r1w0;
            int sh = c0 & 31;
            sacc[j][0] = ((w0sel >> sh) & 1u) ? sacc[j][0] : -CUDART_INF_F;
            sacc[j][1] = ((w0sel >> (sh + 1)) & 1u) ? sacc[j][1] : -CUDART_INF_F;
            sacc[j][2] = ((w1sel >> sh) & 1u) ? sacc[j][2] : -CUDART_INF_F;
            sacc[j][3] = ((w1sel >> (sh + 1)) & 1u) ? sacc[j][3] : -CUDART_INF_F;
            tm0 = fmaxf(tm0, fmaxf(sacc[j][0], sacc[j][1]));
            tm1 = fmaxf(tm1, fmaxf(sacc[j][2], sacc[j][3]));
        }
        tm0 = fmaxf(tm0, __shfl_xor_sync(0xffffffffu, tm0, 1));
        tm0 = fmaxf(tm0, __shfl_xor_sync(0xffffffffu, tm0, 2));
        tm1 = fmaxf(tm1, __shfl_xor_sync(0xffffffffu, tm1, 1));
        tm1 = fmaxf(tm1, __shfl_xor_sync(0xffffffffu, tm1, 2));

        float mn0 = fmaxf(m0, tm0), mn1 = fmaxf(m1, tm1);
        bool any0 = (mn0 > -CUDART_INF_F), any1 = (mn1 > -CUDART_INF_F);
        float al0 = any0 ? __expf(m0 - mn0) : 1.f;
        float al1 = any1 ? __expf(m1 - mn1) : 1.f;
        m0 = mn0; m1 = mn1;

        float rs0 = 0.f, rs1 = 0.f;
        #pragma unroll
        for (int j = 0; j < 8; ++j) {
            float p0 = any0 && (sacc[j][0] > -CUDART_INF_F) ? __expf(sacc[j][0] - mn0) : 0.f;
            float p1 = any0 && (sacc[j][1] > -CUDART_INF_F) ? __expf(sacc[j][1] - mn0) : 0.f;
            float p2 = any1 && (sacc[j][2] > -CUDART_INF_F) ? __expf(sacc[j][2] - mn1) : 0.f;
            float p3 = any1 && (sacc[j][3] > -CUDART_INF_F) ? __expf(sacc[j][3] - mn1) : 0.f;
            sacc[j][0] = p0; sacc[j][1] = p1; sacc[j][2] = p2; sacc[j][3] = p3;
            rs0 += p0 + p1; rs1 += p2 + p3;
        }
        rs0 += __shfl_xor_sync(0xffffffffu, rs0, 1);
        rs0 += __shfl_xor_sync(0xffffffffu, rs0, 2);
        rs1 += __shfl_xor_sync(0xffffffffu, rs1, 1);
        rs1 += __shfl_xor_sync(0xffffffffu, rs1, 2);
        l0 = l0 * al0 + rs0;
        l1 = l1 * al1 + rs1;
        #pragma unroll
        for (int j = 0; j < 8; ++j) {
            oacc[j][0] *= al0; oacc[j][1] *= al0;
            oacc[j][2] *= al1; oacc[j][3] *= al1;
        }

        // ---- GEMM2: O += P V (P stays in registers; C-frag == A-frag layout) ----
        #pragma unroll
        for (int kk = 0; kk < 4; ++kk) {
            uint32_t ah[4], al[4];
            split2(sacc[2*kk][0],   sacc[2*kk][1],   ah[0], al[0]);
            split2(sacc[2*kk][2],   sacc[2*kk][3],   ah[1], al[1]);
            split2(sacc[2*kk+1][0], sacc[2*kk+1][1], ah[2], al[2]);
            split2(sacc[2*kk+1][2], sacc[2*kk+1][3], ah[3], al[3]);
            int bidx = (kk * 8 + lq) * BSTRIDE + g;
            #pragma unroll
            for (int j = 0; j < 8; ++j) {
                uint32_t vh0 = Vhi[bidx + j * 8];
                uint32_t vh1 = Vhi[bidx + j * 8 + 4 * BSTRIDE];
                uint32_t vl0 = Vlo[bidx + j * 8];
                uint32_t vl1 = Vlo[bidx + j * 8 + 4 * BSTRIDE];
                MMA(oacc[j], ah, vh0, vh1);
                MMA(oacc[j], ah, vl0, vl1);
                MMA(oacc[j], al, vh0, vh1);
            }
        }
        __syncthreads();   // before next tile overwrites K/V/mask
    }

    // ---- epilogue: rows w*16+g and w*16+g+8, cols j*8+2lq,+1 ----
    {
        const int row0 = qt * BM + w * 16 + g;
        float inv0 = (l0 > 0.f) ? 1.0f / l0 : 0.f;
        float inv1 = (l1 > 0.f) ? 1.0f / l1 : 0.f;
        float* o0 = out + base + (size_t)row0 * HD;
        float* o1 = o0 + 8 * HD;
        #pragma unroll
        for (int j = 0; j < 8; ++j) {
            int c0 = j * 8 + 2 * lq;
            float2 p0, p1;
            if (l0 > 0.f) { p0.x = oacc[j][0] * inv0; p0.y = oacc[j][1] * inv0; }
            else          { p0.x = g_vmean[bh][c0];   p0.y = g_vmean[bh][c0 + 1]; }
            if (l1 > 0.f) { p1.x = oacc[j][2] * inv1; p1.y = oacc[j][3] * inv1; }
            else          { p1.x = g_vmean[bh][c0];   p1.y = g_vmean[bh][c0 + 1]; }
            *(float2*)(o0 + c0) = p0;
            *(float2*)(o1 + c0) = p1;
        }
    }
}

// ---------------- launch ----------------
extern "C" void kernel_launch(void* const* d_in, const int* in_sizes, int n_in,
                              void* d_out, int out_size) {
    // size-based input identification (hedge against metadata reordering)
    int big[3] = {0, 1, 2}; int nbig = 0; int ip = -1, ib = -1;
    for (int i = 0; i < n_in; ++i) {
        if (in_sizes[i] >= (1 << 20))            { if (nbig < 3) big[nbig++] = i; }
        else if (in_sizes[i] == BATCH * S_LEN)   ip = i;
        else                                     ib = i;
    }
    if (nbig != 3 || ip < 0 || ib < 0) { big[0] = 0; big[1] = 1; big[2] = 2; ip = 3; ib = 4; }

    const float* q = (const float*)d_in[big[0]];
    const float* k = (const float*)d_in[big[1]];
    const float* v = (const float*)d_in[big[2]];
    const unsigned char* praw = (const unsigned char*)d_in[ip];
    const int* sp = (const int*)d_in[ib];
    const int NB = in_sizes[ib];
    float* out = (float*)d_out;

    prep_kernel<<<NQT + 2 * BH + 1, 256>>>(sp, NB, praw, v);
    attn_kernel<<<dim3(NQT, BH), 128>>>(q, k, v, out);
}

// round 7
// speedup vs baseline: 2.1479x; 1.4426x over previous
#include <cuda_runtime.h>
#include <cuda_bf16.h>
#include <math_constants.h>
#include <cstdint>

// Problem constants (fixed by setup_inputs)
#define S_LEN 2048
#define BATCH 4
#define HEADS 8
#define BH    (BATCH*HEADS)        // 32
#define HD    64
#define BM    64                   // q rows per CTA
#define BN    64                   // k cols per tile
#define NQT   (S_LEN/BM)           // 32
#define NKT   (S_LEN/BN)           // 32
#define STRB  72                   // bf16 row stride (144 B): conflict-free LDSM

// ---------------- device scratch ----------------
__device__ unsigned g_mask[S_LEN][S_LEN/32];  // 512 KB museformer bitmask (no pad fold)
__device__ unsigned g_occ64[NQT];             // per-64-row-tile k-tile occupancy
__device__ unsigned g_padw[BATCH][S_LEN/32];  // pad bools as bits
__device__ float    g_vmean[BH][HD];          // fallback: mean of V over S

// ---------------- helpers ----------------
__device__ __forceinline__ unsigned rng_bits(int lo, int hi, int jbase) {
    int a = lo - jbase; a = a < 0 ? 0 : a;
    int b = hi - jbase; b = b > 32 ? 32 : b;
    if (b <= a) return 0u;
    unsigned mb = (b == 32) ? 0xffffffffu : ((1u << b) - 1u);
    unsigned ma = (1u << a) - 1u;
    return mb & ~ma;
}
__device__ __forceinline__ unsigned pt_bit(int p, int jbase) {
    unsigned d = (unsigned)(p - jbase);
    return (d < 32u) ? (1u << d) : 0u;
}

// fp32 pair -> packed bf16x2 hi + lo (residual) words; a = low half
__device__ __forceinline__ void split2(float a, float b, uint32_t& hi, uint32_t& lo) {
    __nv_bfloat16 ha = __float2bfloat16_rn(a);
    __nv_bfloat16 hb = __float2bfloat16_rn(b);
    float ra = a - __bfloat162float(ha);
    float rb = b - __bfloat162float(hb);
    __nv_bfloat16 la = __float2bfloat16_rn(ra);
    __nv_bfloat16 lb = __float2bfloat16_rn(rb);
    hi = ((uint32_t)__bfloat16_as_ushort(hb) << 16) | (uint32_t)__bfloat16_as_ushort(ha);
    lo = ((uint32_t)__bfloat16_as_ushort(lb) << 16) | (uint32_t)__bfloat16_as_ushort(la);
}

// m16n8k16 bf16 MMA, C += A*B  (baseline PTX — works on compute_103 target)
#define MMA(c, a, b0, b1) \
    asm volatile("mma.sync.aligned.m16n8k16.row.col.f32.bf16.bf16.f32 " \
        "{%0,%1,%2,%3}, {%4,%5,%6,%7}, {%8,%9}, {%0,%1,%2,%3};" \
        : "+f"((c)[0]), "+f"((c)[1]), "+f"((c)[2]), "+f"((c)[3]) \
        : "r"((a)[0]), "r"((a)[1]), "r"((a)[2]), "r"((a)[3]), "r"(b0), "r"(b1))

#define LDSM_X4(r0, r1, r2, r3, addr) \
    asm volatile("ldmatrix.sync.aligned.m8n8.x4.shared.b16 {%0,%1,%2,%3}, [%4];" \
        : "=r"(r0), "=r"(r1), "=r"(r2), "=r"(r3) : "r"(addr))
#define LDSM_X4_T(r0, r1, r2, r3, addr) \
    asm volatile("ldmatrix.sync.aligned.m8n8.x4.trans.shared.b16 {%0,%1,%2,%3}, [%4];" \
        : "=r"(r0), "=r"(r1), "=r"(r2), "=r"(r3) : "r"(addr))

// ---------------- fused prep kernel ----------------
__global__ __launch_bounds__(256)
void prep_kernel(const int* __restrict__ sp, int NB,
                 const unsigned char* __restrict__ praw,
                 const float* __restrict__ v) {
    __shared__ int      ssp[256];
    __shared__ unsigned socc[64];
    __shared__ int      flags;
    __shared__ float4   part4[32][8];

    const int tid = threadIdx.x;
    const int blk = blockIdx.x;

    if (blk < NQT) {
        const int qt = blk;
        for (int t = tid; t < NB && t < 256; t += 256) ssp[t] = sp[t];
        if (tid < 64) socc[tid] = 0u;
        __syncthreads();

        for (int p = 0; p < 16; ++p) {
            int cell = tid + p * 256;
            int row = cell >> 6;
            int wdi = cell & 63;
            int i = qt * 64 + row;
            int jbase = wdi * 32;

            int lo = 0, hi = NB;
            while (lo < hi) { int mid = (lo + hi) >> 1; if (ssp[mid] < i) lo = mid + 1; else hi = mid; }
            int c = lo;
            bool is_sum = (c < NB) && (ssp[c] == i);

            unsigned bits;
            if (is_sum) {
                int rlo = (c == 0) ? 1 : ssp[c - 1] + 1;
                bits = rng_bits(rlo, i, jbase);
            } else {
                bool aliasOk = (i + 1 < S_LEN) && !((c < NB) && (ssp[c] == i + 1));
                if (c == 0) {
                    bits = rng_bits(0, i + 1, jbase);
                } else {
                    int fi = ssp[c - 1] + 1;
                    bits = (i > fi) ? rng_bits(fi + 1, i + 1, jbase) : 0u;
                    const int SB[6] = {1, 2, 4, 8, 16, 32};
                    #pragma unroll
                    for (int t6 = 0; t6 < 6; ++t6) {
                        int s = SB[t6];
                        if (c >= s) bits |= pt_bit(ssp[c - s], jbase);
                        if (c > s)  bits |= rng_bits(ssp[c - s - 1] + 1, ssp[c - s] - 1, jbase);
                    }
                }
                if (aliasOk) bits |= pt_bit(i + 1, jbase);
            }
            g_mask[i][wdi] = bits;
            if (bits) atomicOr(&socc[wdi], bits);
        }
        __syncthreads();
        if (tid < 32) {
            unsigned ow = socc[2 * tid] | socc[2 * tid + 1];
            unsigned ball = __ballot_sync(0xffffffffu, ow != 0u);
            if (tid == 0) g_occ64[qt] = ball;
        }
    } else if (blk < NQT + 2 * BH) {
        // ===== vmean =====
        const int q = blk - NQT;
        const int bh = q >> 1, half = q & 1;
        const int dgl = tid & 7;
        const int dg = half * 8 + dgl;
        const int rg = tid >> 3;
        const float4* p = (const float4*)(v + (size_t)bh * S_LEN * HD) + dg;
        const int r0 = rg * 64;

        float4 a0 = {0,0,0,0}, a1 = {0,0,0,0}, a2 = {0,0,0,0}, a3 = {0,0,0,0};
        #pragma unroll 2
        for (int i = 0; i < 64; i += 8) {
            float4 x0 = p[(r0 + i + 0) * (HD/4)];
            float4 x1 = p[(r0 + i + 1) * (HD/4)];
            float4 x2 = p[(r0 + i + 2) * (HD/4)];
            float4 x3 = p[(r0 + i + 3) * (HD/4)];
            float4 x4 = p[(r0 + i + 4) * (HD/4)];
            float4 x5 = p[(r0 + i + 5) * (HD/4)];
            float4 x6 = p[(r0 + i + 6) * (HD/4)];
            float4 x7 = p[(r0 + i + 7) * (HD/4)];
            a0.x += x0.x + x4.x; a0.y += x0.y + x4.y; a0.z += x0.z + x4.z; a0.w += x0.w + x4.w;
            a1.x += x1.x + x5.x; a1.y += x1.y + x5.y; a1.z += x1.z + x5.z; a1.w += x1.w + x5.w;
            a2.x += x2.x + x6.x; a2.y += x2.y + x6.y; a2.z += x2.z + x6.z; a2.w += x2.w + x6.w;
            a3.x += x3.x + x7.x; a3.y += x3.y + x7.y; a3.z += x3.z + x7.z; a3.w += x3.w + x7.w;
        }
        float4 a;
        a.x = (a0.x + a1.x) + (a2.x + a3.x);
        a.y = (a0.y + a1.y) + (a2.y + a3.y);
        a.z = (a0.z + a1.z) + (a2.z + a3.z);
        a.w = (a0.w + a1.w) + (a2.w + a3.w);
        part4[rg][dgl] = a;
        __syncthreads();
        #pragma unroll
        for (int s = 16; s >= 1; s >>= 1) {
            if (rg < s) {
                float4 o = part4[rg][dgl], x = part4[rg + s][dgl];
                o.x += x.x; o.y += x.y; o.z += x.z; o.w += x.w;
                part4[rg][dgl] = o;
            }
            __syncthreads();
        }
        if (rg == 0) {
            float4 a4 = part4[0][dgl];
            const float inv = 1.0f / (float)S_LEN;
            g_vmean[bh][dg * 4 + 0] = a4.x * inv;
            g_vmean[bh][dg * 4 + 1] = a4.y * inv;
            g_vmean[bh][dg * 4 + 2] = a4.z * inv;
            g_vmean[bh][dg * 4 + 3] = a4.w * inv;
        }
    } else {
        // ===== pad canon =====
        if (tid == 0) flags = 0;
        __syncthreads();
        const unsigned* w = (const unsigned*)praw;
        int f = 0;
        for (int i = tid; i < (BATCH * S_LEN) / 4; i += 256) {
            unsigned x = w[i];
            if (x > 1u) f |= 1;
            if (x != 0u && x != 0x3F800000u) f |= 2;
        }
        if (f) atomicOr(&flags, f);
        __syncthreads();
        const int fl = flags;
        const int mode = ((fl & 1) == 0) ? 1 : (((fl & 2) == 0) ? 2 : 0);
        unsigned bits = 0;
        if (mode == 0) { for (int j = 0; j < 32; ++j) if (praw[tid * 32 + j]) bits |= 1u << j; }
        else           { for (int j = 0; j < 32; ++j) if (w[tid * 32 + j])    bits |= 1u << j; }
        ((unsigned*)g_padw)[tid] = bits;
    }
}

// ---------------- sparse flash attention: bf16 hi/lo mma + ldmatrix ----------------
// 4 warps; warp w owns rows w*16..w*16+15. lane: g = lane>>2, lq = lane&3.
// K and V tiles staged in NATURAL row layout [n][d] / [s][d], bf16, stride 72.
__global__ __launch_bounds__(128)
void attn_kernel(const float* __restrict__ q, const float* __restrict__ k,
                 const float* __restrict__ v, float* __restrict__ out) {
    __shared__ __align__(16) __nv_bfloat16 Khi[64 * STRB], Klo[64 * STRB];
    __shared__ __align__(16) __nv_bfloat16 Vhi[64 * STRB], Vlo[64 * STRB];
    __shared__ unsigned mask_sh[BM * 2];

    const int qt  = blockIdx.x;
    const int bh  = blockIdx.y;
    const int b   = bh >> 3;
    const int tid = threadIdx.x;
    const int w   = tid >> 5;
    const int lane = tid & 31;
    const int g   = lane >> 2;
    const int lq  = lane & 3;

    const size_t base = (size_t)bh * S_LEN * HD;

    // per-lane LDSM base addresses (byte offsets into smem window)
    const int rK = (lane & 7) | ((lane >> 1) & 8);   // row-in-16 for K (no trans)
    const int cK = (lane & 8);                       // col-8 offset for K
    const int rV = (lane & 15);                      // row-in-16 for V (trans)
    const int cV = ((lane >> 1) & 8);                // col-8 offset for V
    const uint32_t kB_h = (uint32_t)__cvta_generic_to_shared(Khi) + (uint32_t)(rK * STRB + cK) * 2u;
    const uint32_t kB_l = (uint32_t)__cvta_generic_to_shared(Klo) + (uint32_t)(rK * STRB + cK) * 2u;
    const uint32_t vB_h = (uint32_t)__cvta_generic_to_shared(Vhi) + (uint32_t)(rV * STRB + cV) * 2u;
    const uint32_t vB_l = (uint32_t)__cvta_generic_to_shared(Vlo) + (uint32_t)(rV * STRB + cV) * 2u;

    // ---- preload Q fragments (scale folded), hi/lo ----
    uint32_t Qh[4][4], Ql[4][4];
    {
        const float sc = 0.125f;
        const float* qr0 = q + base + (size_t)(qt * BM + w * 16 + g) * HD;
        const float* qr1 = qr0 + 8 * HD;
        #pragma unroll
        for (int kk = 0; kk < 4; ++kk) {
            int d0 = kk * 16 + 2 * lq;
            float2 x0 = *(const float2*)(qr0 + d0);
            float2 x1 = *(const float2*)(qr1 + d0);
            float2 x2 = *(const float2*)(qr0 + d0 + 8);
            float2 x3 = *(const float2*)(qr1 + d0 + 8);
            split2(x0.x * sc, x0.y * sc, Qh[kk][0], Ql[kk][0]);
            split2(x1.x * sc, x1.y * sc, Qh[kk][1], Ql[kk][1]);
            split2(x2.x * sc, x2.y * sc, Qh[kk][2], Ql[kk][2]);
            split2(x3.x * sc, x3.y * sc, Qh[kk][3], Ql[kk][3]);
        }
    }

    float oacc[8][4];
    #pragma unroll
    for (int j = 0; j < 8; ++j)
        #pragma unroll
        for (int c = 0; c < 4; ++c) oacc[j][c] = 0.f;
    float m0 = -CUDART_INF_F, m1 = -CUDART_INF_F, l0 = 0.f, l1 = 0.f;

    const unsigned occ = g_occ64[qt];

    #pragma unroll 1
    for (int kt = 0; kt < NKT; ++kt) {
        if (!((occ >> kt) & 1u)) continue;

        // ---- stage K tile [n][d] bf16 hi/lo (coalesced) ----
        {
            const int dc = tid & 15, n0 = tid >> 4;
            #pragma unroll
            for (int it = 0; it < 8; ++it) {
                int n = n0 + it * 8;
                float4 x = *(const float4*)(k + base + (size_t)(kt * BN + n) * HD + dc * 4);
                uint32_t h0, h1, q0, q1;
                split2(x.x, x.y, h0, q0);
                split2(x.z, x.w, h1, q1);
                *(uint2*)(Khi + n * STRB + dc * 4) = make_uint2(h0, h1);
                *(uint2*)(Klo + n * STRB + dc * 4) = make_uint2(q0, q1);
            }
        }
        // ---- stage V tile [s][d] bf16 hi/lo (coalesced, natural layout) ----
        {
            const int dc = tid & 15, s0 = tid >> 4;
            #pragma unroll
            for (int it = 0; it < 8; ++it) {
                int s = s0 + it * 8;
                float4 x = *(const float4*)(v + base + (size_t)(kt * BN + s) * HD + dc * 4);
                uint32_t h0, h1, q0, q1;
                split2(x.x, x.y, h0, q0);
                split2(x.z, x.w, h1, q1);
                *(uint2*)(Vhi + s * STRB + dc * 4) = make_uint2(h0, h1);
                *(uint2*)(Vlo + s * STRB + dc * 4) = make_uint2(q0, q1);
            }
        }
        // ---- stage mask words (pad folded) ----
        {
            int rt = tid >> 1, h = tid & 1;
            int grow = qt * BM + rt;
            unsigned rowp = (g_padw[b][grow >> 5] >> (grow & 31)) & 1u;
            mask_sh[tid] = rowp ? (g_mask[grow][2 * kt + h] & g_padw[b][2 * kt + h]) : 0u;
        }
        __syncthreads();

        // ---- GEMM1: S = Q K^T (3-pass hi/lo, LDSM B-frags) ----
        float sacc[8][4];
        #pragma unroll
        for (int j = 0; j < 8; ++j)
            #pragma unroll
            for (int c = 0; c < 4; ++c) sacc[j][c] = 0.f;

        #pragma unroll
        for (int kk = 0; kk < 4; ++kk) {
            #pragma unroll
            for (int jn = 0; jn < 4; ++jn) {
                uint32_t off = (uint32_t)(jn * 16 * STRB + kk * 16) * 2u;
                uint32_t h0, h1, h2, h3, e0, e1, e2, e3;
                LDSM_X4(h0, h1, h2, h3, kB_h + off);
                LDSM_X4(e0, e1, e2, e3, kB_l + off);
                MMA(sacc[2*jn],   Qh[kk], h0, h1);
                MMA(sacc[2*jn],   Qh[kk], e0, e1);
                MMA(sacc[2*jn],   Ql[kk], h0, h1);
                MMA(sacc[2*jn+1], Qh[kk], h2, h3);
                MMA(sacc[2*jn+1], Qh[kk], e2, e3);
                MMA(sacc[2*jn+1], Ql[kk], h2, h3);
            }
        }

        // ---- masked online softmax (rows g and g+8) ----
        unsigned r0w0 = mask_sh[(w * 16 + g) * 2],     r0w1 = mask_sh[(w * 16 + g) * 2 + 1];
        unsigned r1w0 = mask_sh[(w * 16 + g + 8) * 2], r1w1 = mask_sh[(w * 16 + g + 8) * 2 + 1];

        float tm0 = -CUDART_INF_F, tm1 = -CUDART_INF_F;
        #pragma unroll
        for (int j = 0; j < 8; ++j) {
            int c0 = j * 8 + 2 * lq;
            unsigned w0sel = (c0 & 32) ? r0w1 : r0w0;
            unsigned w1sel = (c0 & 32) ? r1w1 : r1w0;
            int sh = c0 & 31;
            sacc[j][0] = ((w0sel >> sh) & 1u) ? sacc[j][0] : -CUDART_INF_F;
            sacc[j][1] = ((w0sel >> (sh + 1)) & 1u) ? sacc[j][1] : -CUDART_INF_F;
            sacc[j][2] = ((w1sel >> sh) & 1u) ? sacc[j][2] : -CUDART_INF_F;
            sacc[j][3] = ((w1sel >> (sh + 1)) & 1u) ? sacc[j][3] : -CUDART_INF_F;
            tm0 = fmaxf(tm0, fmaxf(sacc[j][0], sacc[j][1]));
            tm1 = fmaxf(tm1, fmaxf(sacc[j][2], sacc[j][3]));
        }
        tm0 = fmaxf(tm0, __shfl_xor_sync(0xffffffffu, tm0, 1));
        tm0 = fmaxf(tm0, __shfl_xor_sync(0xffffffffu, tm0, 2));
        tm1 = fmaxf(tm1, __shfl_xor_sync(0xffffffffu, tm1, 1));
        tm1 = fmaxf(tm1, __shfl_xor_sync(0xffffffffu, tm1, 2));

        float mn0 = fmaxf(m0, tm0), mn1 = fmaxf(m1, tm1);
        bool any0 = (mn0 > -CUDART_INF_F), any1 = (mn1 > -CUDART_INF_F);
        float al0 = any0 ? __expf(m0 - mn0) : 1.f;
        float al1 = any1 ? __expf(m1 - mn1) : 1.f;
        m0 = mn0; m1 = mn1;

        float rs0 = 0.f, rs1 = 0.f;
        #pragma unroll
        for (int j = 0; j < 8; ++j) {
            float p0 = any0 && (sacc[j][0] > -CUDART_INF_F) ? __expf(sacc[j][0] - mn0) : 0.f;
            float p1 = any0 && (sacc[j][1] > -CUDART_INF_F) ? __expf(sacc[j][1] - mn0) : 0.f;
            float p2 = any1 && (sacc[j][2] > -CUDART_INF_F) ? __expf(sacc[j][2] - mn1) : 0.f;
            float p3 = any1 && (sacc[j][3] > -CUDART_INF_F) ? __expf(sacc[j][3] - mn1) : 0.f;
            sacc[j][0] = p0; sacc[j][1] = p1; sacc[j][2] = p2; sacc[j][3] = p3;
            rs0 += p0 + p1; rs1 += p2 + p3;
        }
        rs0 += __shfl_xor_sync(0xffffffffu, rs0, 1);
        rs0 += __shfl_xor_sync(0xffffffffu, rs0, 2);
        rs1 += __shfl_xor_sync(0xffffffffu, rs1, 1);
        rs1 += __shfl_xor_sync(0xffffffffu, rs1, 2);
        l0 = l0 * al0 + rs0;
        l1 = l1 * al1 + rs1;
        #pragma unroll
        for (int j = 0; j < 8; ++j) {
            oacc[j][0] *= al0; oacc[j][1] *= al0;
            oacc[j][2] *= al1; oacc[j][3] *= al1;
        }

        // ---- GEMM2: O += P V (P in registers; LDSM.trans B-frags) ----
        #pragma unroll
        for (int sk = 0; sk < 4; ++sk) {
            uint32_t ah[4], al[4];
            split2(sacc[2*sk][0],   sacc[2*sk][1],   ah[0], al[0]);
            split2(sacc[2*sk][2],   sacc[2*sk][3],   ah[1], al[1]);
            split2(sacc[2*sk+1][0], sacc[2*sk+1][1], ah[2], al[2]);
            split2(sacc[2*sk+1][2], sacc[2*sk+1][3], ah[3], al[3]);
            #pragma unroll
            for (int jd = 0; jd < 4; ++jd) {
                uint32_t off = (uint32_t)(sk * 16 * STRB + jd * 16) * 2u;
                uint32_t h0, h1, h2, h3, e0, e1, e2, e3;
                LDSM_X4_T(h0, h1, h2, h3, vB_h + off);
                LDSM_X4_T(e0, e1, e2, e3, vB_l + off);
                MMA(oacc[2*jd],   ah, h0, h1);
                MMA(oacc[2*jd],   ah, e0, e1);
                MMA(oacc[2*jd],   al, h0, h1);
                MMA(oacc[2*jd+1], ah, h2, h3);
                MMA(oacc[2*jd+1], ah, e2, e3);
                MMA(oacc[2*jd+1], al, h2, h3);
            }
        }
        __syncthreads();   // before next tile overwrites K/V/mask
    }

    // ---- epilogue: rows w*16+g and w*16+g+8, cols j*8+2lq,+1 ----
    {
        const int row0 = qt * BM + w * 16 + g;
        float inv0 = (l0 > 0.f) ? 1.0f / l0 : 0.f;
        float inv1 = (l1 > 0.f) ? 1.0f / l1 : 0.f;
        float* o0 = out + base + (size_t)row0 * HD;
        float* o1 = o0 + 8 * HD;
        #pragma unroll
        for (int j = 0; j < 8; ++j) {
            int c0 = j * 8 + 2 * lq;
            float2 p0, p1;
            if (l0 > 0.f) { p0.x = oacc[j][0] * inv0; p0.y = oacc[j][1] * inv0; }
            else          { p0.x = g_vmean[bh][c0];   p0.y = g_vmean[bh][c0 + 1]; }
            if (l1 > 0.f) { p1.x = oacc[j][2] * inv1; p1.y = oacc[j][3] * inv1; }
            else          { p1.x = g_vmean[bh][c0];   p1.y = g_vmean[bh][c0 + 1]; }
            *(float2*)(o0 + c0) = p0;
            *(float2*)(o1 + c0) = p1;
        }
    }
}

// ---------------- launch ----------------
extern "C" void kernel_launch(void* const* d_in, const int* in_sizes, int n_in,
                              void* d_out, int out_size) {
    // size-based input identification (hedge against metadata reordering)
    int big[3] = {0, 1, 2}; int nbig = 0; int ip = -1, ib = -1;
    for (int i = 0; i < n_in; ++i) {
        if (in_sizes[i] >= (1 << 20))            { if (nbig < 3) big[nbig++] = i; }
        else if (in_sizes[i] == BATCH * S_LEN)   ip = i;
        else                                     ib = i;
    }
    if (nbig != 3 || ip < 0 || ib < 0) { big[0] = 0; big[1] = 1; big[2] = 2; ip = 3; ib = 4; }

    const float* q = (const float*)d_in[big[0]];
    const float* k = (const float*)d_in[big[1]];
    const float* v = (const float*)d_in[big[2]];
    const unsigned char* praw = (const unsigned char*)d_in[ip];
    const int* sp = (const int*)d_in[ib];
    const int NB = in_sizes[ib];
    float* out = (float*)d_out;

    prep_kernel<<<NQT + 2 * BH + 1, 256>>>(sp, NB, praw, v);
    attn_kernel<<<dim3(NQT, BH), 128>>>(q, k, v, out);
}